// round 7
// baseline (speedup 1.0000x reference)
#include <cuda_runtime.h>
#include <math.h>
#include <stdint.h>

#define K_SIZE 41
#define WBLK   256

// Pattern byte-period: 41 floats * 4 B = 164 B; lcm(164,16) = 656 B = 41 float4s.
#define PERIOD_BYTES 656
#define OP_PERIODS   64
#define OP_BYTES     (PERIOD_BYTES * OP_PERIODS)   // 41984 B per bulk store
#define SBUF_F4      (OP_BYTES / 16)               // 2624 float4s

#define WGRID 592   // 4 blocks/SM on 148 SMs

// Period-41 table of float4 write patterns, produced by prep kernel.
// g_pat[p] covers output floats 4p..4p+3.
__device__ float4 g_pat[K_SIZE];

// ---------------------------------------------------------------------------
// Prep: 1 block, 64 threads. Computes padded window, masked circular max ->
// base[41], expands to float4 pattern table, and writes the tail floats not
// covered by whole 656-B periods (33 of them for N=33554433).
// ---------------------------------------------------------------------------
__global__ void flatdil_prep_kernel(const float* __restrict__ in,
                                    const float* __restrict__ scale_p,
                                    float* __restrict__ out,
                                    long long n,
                                    long long tail_start)
{
    __shared__ float s_pad[K_SIZE];
    __shared__ float s_base[K_SIZE];

    const int t = threadIdx.x;

    // Python: missing = K_SIZE - n; a = -(missing // 2 + 2)  (floor division)
    const long long missing = (long long)K_SIZE - n;
    const long long a = -((missing >> 1) + 2);   // arithmetic shift == floor div

    if (t < K_SIZE) {
        s_pad[t] = in[a + (long long)t];
    }
    __syncthreads();

    if (t < K_SIZE) {
        const float scale = *scale_p;
        float acc = -INFINITY;
        #pragma unroll
        for (int j = 0; j < K_SIZE; ++j) {
            // z[j] = -20 + j  (linspace(-20,20,41) has exact unit step)
            const float zj = (float)(j - 20);
            if (fabsf(zj) <= scale) {
                int idx = t + j;
                if (idx >= K_SIZE) idx -= K_SIZE;
                acc = fmaxf(acc, s_pad[idx]);
            }
        }
        s_base[t] = acc;
    }
    __syncthreads();

    if (t < K_SIZE) {
        int i0 = (4 * t) % K_SIZE;
        int i1 = i0 + 1; if (i1 >= K_SIZE) i1 -= K_SIZE;
        int i2 = i1 + 1; if (i2 >= K_SIZE) i2 -= K_SIZE;
        int i3 = i2 + 1; if (i3 >= K_SIZE) i3 -= K_SIZE;
        float4 v;
        v.x = s_base[i0];
        v.y = s_base[i1];
        v.z = s_base[i2];
        v.w = s_base[i3];
        g_pat[t] = v;
    }

    // Tail not covered by whole 656-B periods (tail_start .. n-1, <= 163 elems)
    if (t == 0) {
        for (long long k = tail_start; k < n; ++k) {
            out[k] = s_base[(int)(k % K_SIZE)];
        }
    }
}

// ---------------------------------------------------------------------------
// TMA bulk-store writer. Each block builds one 41984-B repeating-pattern
// buffer in shared (read-only afterwards), then thread 0 issues
// cp.async.bulk shared->global ops of 41984 B at 41984-B-aligned global
// offsets (pattern phase 0 at every chunk start). Whole 134 MB output =
// ~3197 bulk ops chip-wide; the L1/LSU per-thread store path is bypassed.
// ---------------------------------------------------------------------------
__global__ void __launch_bounds__(WBLK)
flatdil_bulk_write_kernel(float* __restrict__ out,
                          unsigned long long total_bytes)
{
    __shared__ float4 s_pat[K_SIZE];
    __shared__ __align__(16) float4 s_buf[SBUF_F4];

    const int t = threadIdx.x;
    if (t < K_SIZE) s_pat[t] = g_pat[t];
    __syncthreads();

    // Expand the 41-float4 pattern to 64 full periods (2624 float4s).
    for (int i = t; i < SBUF_F4; i += WBLK) {
        s_buf[i] = s_pat[i % K_SIZE];
    }
    __syncthreads();
    // Order generic smem writes before async-proxy (TMA) reads of smem.
    asm volatile("fence.proxy.async.shared::cta;" ::: "memory");

    if (t == 0) {
        uint32_t s_addr;
        asm("{ .reg .u64 tmp; cvta.to.shared.u64 tmp, %1; cvt.u32.u64 %0, tmp; }"
            : "=r"(s_addr) : "l"(s_buf));

        unsigned long long off    = (unsigned long long)blockIdx.x * OP_BYTES;
        const unsigned long long stride = (unsigned long long)WGRID * OP_BYTES;

        for (; off < total_bytes; off += stride) {
            unsigned long long rem = total_bytes - off;
            unsigned int sz = (rem < (unsigned long long)OP_BYTES)
                                ? (unsigned int)rem : (unsigned int)OP_BYTES;
            char* g = (char*)out + off;
            asm volatile(
                "cp.async.bulk.global.shared::cta.bulk_group [%0], [%1], %2;"
                :: "l"(g), "r"(s_addr), "r"(sz) : "memory");
        }
        asm volatile("cp.async.bulk.commit_group;" ::: "memory");
        asm volatile("cp.async.bulk.wait_group 0;" ::: "memory");
    }
}

// ---------------------------------------------------------------------------
extern "C" void kernel_launch(void* const* d_in, const int* in_sizes, int n_in,
                              void* d_out, int out_size)
{
    const float* in      = (const float*)d_in[0];
    const float* scale_p = (const float*)d_in[1];
    float* out           = (float*)d_out;

    const long long n = (long long)in_sizes[0];

    // Bytes covered by whole 656-B periods (each also a whole float4 region).
    const long long n4           = n >> 2;                      // full float4s
    const long long full_periods = n4 / K_SIZE;                 // 656-B periods
    const unsigned long long bulk_bytes =
        (unsigned long long)full_periods * PERIOD_BYTES;
    const long long tail_start = (long long)(bulk_bytes / 4);   // first tail float

    flatdil_prep_kernel<<<1, 64>>>(in, scale_p, out, n, tail_start);

    if (bulk_bytes > 0) {
        flatdil_bulk_write_kernel<<<WGRID, WBLK>>>(out, bulk_bytes);
    }
}

// round 12
// speedup vs baseline: 1.1813x; 1.1813x over previous
#include <cuda_runtime.h>
#include <math.h>

#define K_SIZE 41

// Period-41 table of float4 write patterns, produced by prep kernel.
__device__ float4 g_pat[K_SIZE];

// ---------------------------------------------------------------------------
// Prep: 1 block. Compute padded window, masked circular max -> base[41],
// expand to float4 pattern table, and write the <=3 tail scalars of out.
// ---------------------------------------------------------------------------
__global__ void flatdil_prep_kernel(const float* __restrict__ in,
                                    const float* __restrict__ scale_p,
                                    float* __restrict__ out,
                                    long long n)
{
    __shared__ float s_pad[K_SIZE];
    __shared__ float s_base[K_SIZE];

    const int t = threadIdx.x;
    const float scale = *scale_p;

    // Python: missing = K_SIZE - n; a = -(missing // 2 + 2)   (floor division)
    const long long missing = (long long)K_SIZE - n;
    const long long a = -((missing >> 1) + 2);   // arithmetic shift == floor div by 2

    if (t < K_SIZE) {
        s_pad[t] = in[a + (long long)t];
    }
    __syncthreads();

    if (t < K_SIZE) {
        float acc = -INFINITY;
        #pragma unroll
        for (int j = 0; j < K_SIZE; ++j) {
            // z[j] = -20 + j (linspace(-20,20,41) has exact unit step)
            const float zj = (float)(j - 20);
            if (fabsf(zj) <= scale) {
                int idx = t + j;
                if (idx >= K_SIZE) idx -= K_SIZE;
                acc = fmaxf(acc, s_pad[idx]);
            }
        }
        s_base[t] = acc;
    }
    __syncthreads();

    if (t < K_SIZE) {
        // g_pat[p] covers output floats 4p..4p+3 (pattern period in float4s = 41)
        int i0 = (4 * t) % K_SIZE;
        int i1 = i0 + 1; if (i1 >= K_SIZE) i1 -= K_SIZE;
        int i2 = i1 + 1; if (i2 >= K_SIZE) i2 -= K_SIZE;
        int i3 = i2 + 1; if (i3 >= K_SIZE) i3 -= K_SIZE;
        float4 v;
        v.x = s_base[i0];
        v.y = s_base[i1];
        v.z = s_base[i2];
        v.w = s_base[i3];
        g_pat[t] = v;
    }

    // Tail: elements not covered by the float4 writer (<= 3 of them)
    if (t == 0) {
        long long n4 = n >> 2;          // number of full float4s
        for (long long k = n4 * 4; k < n; ++k) {
            out[k] = s_base[(int)(k % K_SIZE)];
        }
    }
}

// ---------------------------------------------------------------------------
// Writer: one STG.128 per thread. Pattern staged in shared (656 B) so global
// read traffic is ~21 MB total instead of 537 MB.
// ---------------------------------------------------------------------------
__global__ void __launch_bounds__(256)
flatdil_write_kernel(float4* __restrict__ out4, unsigned int n4)
{
    __shared__ float4 s_pat[K_SIZE];
    const unsigned int t = threadIdx.x;
    if (t < K_SIZE) s_pat[t] = g_pat[t];
    __syncthreads();

    const unsigned int i = blockIdx.x * 256u + t;
    if (i < n4) {
        out4[i] = s_pat[i % K_SIZE];
    }
}

// ---------------------------------------------------------------------------
extern "C" void kernel_launch(void* const* d_in, const int* in_sizes, int n_in,
                              void* d_out, int out_size)
{
    const float* in      = (const float*)d_in[0];
    const float* scale_p = (const float*)d_in[1];
    float* out           = (float*)d_out;

    const long long n  = (long long)in_sizes[0];
    const long long n4 = n >> 2;

    flatdil_prep_kernel<<<1, 64>>>(in, scale_p, out, n);

    if (n4 > 0) {
        unsigned int blocks = (unsigned int)((n4 + 255) / 256);
        flatdil_write_kernel<<<blocks, 256>>>((float4*)out, (unsigned int)n4);
    }
}

// round 13
// speedup vs baseline: 1.1841x; 1.0024x over previous
#include <cuda_runtime.h>
#include <math.h>

#define K_SIZE 41

// Period-41 table of float4 write patterns, produced by prep kernel.
__device__ float4 g_pat[K_SIZE];

// ---------------------------------------------------------------------------
// Prep: 1 block. Compute padded window, masked circular max -> base[41],
// expand to float4 pattern table, and write the <=3 tail scalars of out.
// ---------------------------------------------------------------------------
__global__ void flatdil_prep_kernel(const float* __restrict__ in,
                                    const float* __restrict__ scale_p,
                                    float* __restrict__ out,
                                    long long n)
{
    __shared__ float s_pad[K_SIZE];
    __shared__ float s_base[K_SIZE];

    const int t = threadIdx.x;
    const float scale = *scale_p;

    // Python: missing = K_SIZE - n; a = -(missing // 2 + 2)   (floor division)
    const long long missing = (long long)K_SIZE - n;
    const long long a = -((missing >> 1) + 2);   // arithmetic shift == floor div by 2

    if (t < K_SIZE) {
        s_pad[t] = in[a + (long long)t];
    }
    __syncthreads();

    if (t < K_SIZE) {
        float acc = -INFINITY;
        #pragma unroll
        for (int j = 0; j < K_SIZE; ++j) {
            // z[j] = -20 + j (linspace(-20,20,41) has exact unit step)
            const float zj = (float)(j - 20);
            if (fabsf(zj) <= scale) {
                int idx = t + j;
                if (idx >= K_SIZE) idx -= K_SIZE;
                acc = fmaxf(acc, s_pad[idx]);
            }
        }
        s_base[t] = acc;
    }
    __syncthreads();

    if (t < K_SIZE) {
        // g_pat[p] covers output floats 4p..4p+3 (pattern period in float4s = 41)
        int i0 = (4 * t) % K_SIZE;
        int i1 = i0 + 1; if (i1 >= K_SIZE) i1 -= K_SIZE;
        int i2 = i1 + 1; if (i2 >= K_SIZE) i2 -= K_SIZE;
        int i3 = i2 + 1; if (i3 >= K_SIZE) i3 -= K_SIZE;
        float4 v;
        v.x = s_base[i0];
        v.y = s_base[i1];
        v.z = s_base[i2];
        v.w = s_base[i3];
        g_pat[t] = v;
    }

    // Tail: elements not covered by the float4 writer (<= 3 of them)
    if (t == 0) {
        long long n4 = n >> 2;          // number of full float4s
        for (long long k = n4 * 4; k < n; ++k) {
            out[k] = s_base[(int)(k % K_SIZE)];
        }
    }
}

// ---------------------------------------------------------------------------
// Writer: one STG.128 per thread. Pattern staged in shared (656 B) so global
// read traffic is ~21 MB total instead of 537 MB.
// ---------------------------------------------------------------------------
__global__ void __launch_bounds__(256)
flatdil_write_kernel(float4* __restrict__ out4, unsigned int n4)
{
    __shared__ float4 s_pat[K_SIZE];
    const unsigned int t = threadIdx.x;
    if (t < K_SIZE) s_pat[t] = g_pat[t];
    __syncthreads();

    const unsigned int i = blockIdx.x * 256u + t;
    if (i < n4) {
        out4[i] = s_pat[i % K_SIZE];
    }
}

// ---------------------------------------------------------------------------
extern "C" void kernel_launch(void* const* d_in, const int* in_sizes, int n_in,
                              void* d_out, int out_size)
{
    const float* in      = (const float*)d_in[0];
    const float* scale_p = (const float*)d_in[1];
    float* out           = (float*)d_out;

    const long long n  = (long long)in_sizes[0];
    const long long n4 = n >> 2;

    flatdil_prep_kernel<<<1, 64>>>(in, scale_p, out, n);

    if (n4 > 0) {
        unsigned int blocks = (unsigned int)((n4 + 255) / 256);
        flatdil_write_kernel<<<blocks, 256>>>((float4*)out, (unsigned int)n4);
    }
}

// round 14
// speedup vs baseline: 1.2567x; 1.0613x over previous
#include <cuda_runtime.h>
#include <math.h>

#define K_SIZE 41

// Period-41 table of float4 write patterns, produced by prep kernel.
__device__ float4 g_pat[K_SIZE];

// ---------------------------------------------------------------------------
// Prep: 1 block. Compute padded window, masked circular max -> base[41],
// expand to float4 pattern table, and write the <=3 tail scalars of out.
// ---------------------------------------------------------------------------
__global__ void flatdil_prep_kernel(const float* __restrict__ in,
                                    const float* __restrict__ scale_p,
                                    float* __restrict__ out,
                                    long long n)
{
    __shared__ float s_pad[K_SIZE];
    __shared__ float s_base[K_SIZE];

    const int t = threadIdx.x;
    const float scale = *scale_p;

    // Python: missing = K_SIZE - n; a = -(missing // 2 + 2)   (floor division)
    const long long missing = (long long)K_SIZE - n;
    const long long a = -((missing >> 1) + 2);   // arithmetic shift == floor div by 2

    if (t < K_SIZE) {
        s_pad[t] = in[a + (long long)t];
    }
    __syncthreads();

    if (t < K_SIZE) {
        float acc = -INFINITY;
        #pragma unroll
        for (int j = 0; j < K_SIZE; ++j) {
            // z[j] = -20 + j (linspace(-20,20,41) has exact unit step)
            const float zj = (float)(j - 20);
            if (fabsf(zj) <= scale) {
                int idx = t + j;
                if (idx >= K_SIZE) idx -= K_SIZE;
                acc = fmaxf(acc, s_pad[idx]);
            }
        }
        s_base[t] = acc;
    }
    __syncthreads();

    if (t < K_SIZE) {
        // g_pat[p] covers output floats 4p..4p+3 (pattern period in float4s = 41)
        int i0 = (4 * t) % K_SIZE;
        int i1 = i0 + 1; if (i1 >= K_SIZE) i1 -= K_SIZE;
        int i2 = i1 + 1; if (i2 >= K_SIZE) i2 -= K_SIZE;
        int i3 = i2 + 1; if (i3 >= K_SIZE) i3 -= K_SIZE;
        float4 v;
        v.x = s_base[i0];
        v.y = s_base[i1];
        v.z = s_base[i2];
        v.w = s_base[i3];
        g_pat[t] = v;
    }

    // Tail: elements not covered by the float4 writer (<= 3 of them)
    if (t == 0) {
        long long n4 = n >> 2;          // number of full float4s
        for (long long k = n4 * 4; k < n; ++k) {
            out[k] = s_base[(int)(k % K_SIZE)];
        }
    }
}

// ---------------------------------------------------------------------------
// Writer: one STG.128 per thread. Pattern staged in shared (656 B) so global
// read traffic is ~21 MB total instead of 537 MB.
// ---------------------------------------------------------------------------
__global__ void __launch_bounds__(256)
flatdil_write_kernel(float4* __restrict__ out4, unsigned int n4)
{
    __shared__ float4 s_pat[K_SIZE];
    const unsigned int t = threadIdx.x;
    if (t < K_SIZE) s_pat[t] = g_pat[t];
    __syncthreads();

    const unsigned int i = blockIdx.x * 256u + t;
    if (i < n4) {
        out4[i] = s_pat[i % K_SIZE];
    }
}

// ---------------------------------------------------------------------------
extern "C" void kernel_launch(void* const* d_in, const int* in_sizes, int n_in,
                              void* d_out, int out_size)
{
    const float* in      = (const float*)d_in[0];
    const float* scale_p = (const float*)d_in[1];
    float* out           = (float*)d_out;

    const long long n  = (long long)in_sizes[0];
    const long long n4 = n >> 2;

    flatdil_prep_kernel<<<1, 64>>>(in, scale_p, out, n);

    if (n4 > 0) {
        unsigned int blocks = (unsigned int)((n4 + 255) / 256);
        flatdil_write_kernel<<<blocks, 256>>>((float4*)out, (unsigned int)n4);
    }
}